// round 2
// baseline (speedup 1.0000x reference)
#include <cuda_runtime.h>
#include <cuda_bf16.h>
#include <math.h>

// Problem constants
#define Bb 4
#define Ll 1024
#define OBS 128
#define DM 1024
#define LAT 16
#define DS 16
#define DC 4
#define DI 2048          // 2*DM
#define DTR 64           // DM/16
#define Mrows 4096       // B*L

// ---------------- scratch (device globals; no allocation allowed) ----------
__device__ float g_h  [(size_t)Mrows * DM];        // 16 MB
__device__ float g_xz [(size_t)Mrows * (2*DI)];    // 64 MB
__device__ float g_xc [(size_t)Mrows * DI];        // 32 MB  (post conv+silu)
__device__ float g_dbc[(size_t)Mrows * 96];        // 1.5 MB
__device__ float g_dt [(size_t)Mrows * DI];        // 32 MB
__device__ float g_yg [(size_t)Mrows * DI];        // 32 MB  (y * silu(z))
__device__ float g_hs [(size_t)Mrows * DM];        // 16 MB

// ---------------- generic tiled SGEMM: C = A(MxK, lda) * W(NxK row-major)^T -
// EPI: 0 = none, 1 = +bias[n], 2 = softplus(acc + bias[n])
template<int EPI>
__global__ __launch_bounds__(256)
void gemm_tn(const float* __restrict__ A, int lda,
             const float* __restrict__ W,   // (N,K) row-major
             float* __restrict__ C, int ldc,
             int M, int N, int K,
             const float* __restrict__ bias)
{
    const int BM = 64, BN = 64, BK = 16;
    __shared__ float As[BK][BM + 4];
    __shared__ float Ws[BK][BN + 4];

    const int bm = blockIdx.y * BM;
    const int bn = blockIdx.x * BN;
    const int tid = threadIdx.x;          // 256 threads
    const int tm = tid >> 4;              // 0..15
    const int tn = tid & 15;              // 0..15

    float acc[4][4];
#pragma unroll
    for (int i = 0; i < 4; i++)
#pragma unroll
        for (int j = 0; j < 4; j++) acc[i][j] = 0.f;

    for (int k0 = 0; k0 < K; k0 += BK) {
        // load A tile (64 rows x 16 k), 4 elems/thread
#pragma unroll
        for (int i = 0; i < 4; i++) {
            int e = tid + i * 256;
            int r = e >> 4, c = e & 15;
            int gm = bm + r;
            float v = 0.f;
            if (gm < M) v = A[(size_t)gm * lda + (k0 + c)];
            As[c][r] = v;
        }
        // load W tile (64 n-rows x 16 k)
#pragma unroll
        for (int i = 0; i < 4; i++) {
            int e = tid + i * 256;
            int r = e >> 4, c = e & 15;
            int gn = bn + r;
            float v = 0.f;
            if (gn < N) v = W[(size_t)gn * K + (k0 + c)];
            Ws[c][r] = v;
        }
        __syncthreads();

#pragma unroll
        for (int kk = 0; kk < BK; kk++) {
            float ra[4], rb[4];
#pragma unroll
            for (int i = 0; i < 4; i++) ra[i] = As[kk][tm * 4 + i];
#pragma unroll
            for (int j = 0; j < 4; j++) rb[j] = Ws[kk][tn * 4 + j];
#pragma unroll
            for (int i = 0; i < 4; i++)
#pragma unroll
                for (int j = 0; j < 4; j++)
                    acc[i][j] = fmaf(ra[i], rb[j], acc[i][j]);
        }
        __syncthreads();
    }

#pragma unroll
    for (int i = 0; i < 4; i++) {
        int gm = bm + tm * 4 + i;
        if (gm >= M) continue;
#pragma unroll
        for (int j = 0; j < 4; j++) {
            int gn = bn + tn * 4 + j;
            if (gn >= N) continue;
            float v = acc[i][j];
            if (EPI >= 1) v += bias[gn];
            if (EPI == 2) {
                // stable softplus: max(x,0) + log1p(exp(-|x|))
                float x = v;
                v = fmaxf(x, 0.f) + log1pf(__expf(-fabsf(x)));
            }
            C[(size_t)gm * ldc + gn] = v;
        }
    }
}

// ---------------- depthwise causal conv (kernel=4) + bias + silu -----------
__global__ __launch_bounds__(256)
void conv_silu_kernel(const float* __restrict__ xz,
                      const float* __restrict__ conv_w,
                      const float* __restrict__ conv_b,
                      float* __restrict__ xc)
{
    int t = blockIdx.x;   // 0..L-1
    int b = blockIdx.y;   // 0..B-1
    size_t rowbase = ((size_t)b * Ll + t) * (2 * DI);
    size_t outbase = ((size_t)b * Ll + t) * DI;
    for (int d = threadIdx.x; d < DI; d += 256) {
        float acc = conv_b[d];
        const float* w = conv_w + d * DC;
#pragma unroll
        for (int j = 0; j < DC; j++) {
            int tt = t - (DC - 1) + j;
            if (tt >= 0)
                acc = fmaf(w[j], xz[((size_t)b * Ll + tt) * (2 * DI) + d], acc);
        }
        (void)rowbase;
        float s = acc / (1.f + __expf(-acc));   // silu
        xc[outbase + d] = s;
    }
}

// ---------------- selective scan + D-skip + silu(z) gate -------------------
// 4 lanes per channel (4 states each), 64 channels per 256-thread block.
#define TCH 128
__global__ __launch_bounds__(256)
void scan_kernel(const float* __restrict__ xc,
                 const float* __restrict__ dtb,
                 const float* __restrict__ dbc,
                 const float* __restrict__ xz,      // for z
                 const float* __restrict__ A_log,
                 const float* __restrict__ D_skip,
                 float* __restrict__ ygate)
{
    const int b    = blockIdx.x >> 5;       // grid = B * 32
    const int dblk = blockIdx.x & 31;
    const int tid  = threadIdx.x;
    const int q    = tid & 3;               // sub-thread: states [4q,4q+4)
    const int dl   = tid >> 2;              // local channel 0..63
    const int d    = dblk * 64 + dl;

    float Areg[4], s[4];
#pragma unroll
    for (int j = 0; j < 4; j++) {
        Areg[j] = -__expf(A_log[(size_t)d * DS + q * 4 + j]);
        s[j] = 0.f;
    }
    const float Dv = D_skip[d];

    __shared__ float BC[TCH][32];           // per-t: B[16] then C[16]

    for (int t0 = 0; t0 < Ll; t0 += TCH) {
        __syncthreads();
        for (int e = tid; e < TCH * 32; e += 256) {
            int tt = e >> 5, c = e & 31;
            BC[tt][c] = dbc[((size_t)b * Ll + t0 + tt) * 96 + DTR + c];
        }
        __syncthreads();

        for (int ti = 0; ti < TCH; ti++) {
            size_t row = (size_t)b * Ll + t0 + ti;
            float u   = xc [row * DI + d];
            float dtv = dtb[row * DI + d];
            float du  = dtv * u;
            float y = 0.f;
#pragma unroll
            for (int j = 0; j < 4; j++) {
                float e = __expf(dtv * Areg[j]);
                s[j] = fmaf(s[j], e, du * BC[ti][q * 4 + j]);
                y = fmaf(s[j], BC[ti][16 + q * 4 + j], y);
            }
            y += __shfl_xor_sync(0xffffffffu, y, 1);
            y += __shfl_xor_sync(0xffffffffu, y, 2);
            if (q == 0) {
                float z = xz[row * (2 * DI) + DI + d];
                float g = z / (1.f + __expf(-z));
                ygate[row * DI + d] = (y + u * Dv) * g;
            }
        }
    }
}

// ---------------- launch ---------------------------------------------------
extern "C" void kernel_launch(void* const* d_in, const int* in_sizes, int n_in,
                              void* d_out, int out_size)
{
    const float* x        = (const float*)d_in[0];
    const float* W_enc    = (const float*)d_in[1];
    const float* b_enc    = (const float*)d_in[2];
    const float* W_in     = (const float*)d_in[3];
    const float* conv_w   = (const float*)d_in[4];
    const float* conv_b   = (const float*)d_in[5];
    const float* W_xproj  = (const float*)d_in[6];
    const float* W_dtproj = (const float*)d_in[7];
    const float* dt_bias  = (const float*)d_in[8];
    const float* A_log    = (const float*)d_in[9];
    const float* D_skip   = (const float*)d_in[10];
    const float* W_out    = (const float*)d_in[11];
    const float* W_dec    = (const float*)d_in[12];
    const float* b_dec    = (const float*)d_in[13];
    const float* W_lat    = (const float*)d_in[14];
    const float* b_lat    = (const float*)d_in[15];
    float* out = (float*)d_out;

    float *h, *xz, *xc, *dbc, *dt, *yg, *hs;
    cudaGetSymbolAddress((void**)&h,   g_h);
    cudaGetSymbolAddress((void**)&xz,  g_xz);
    cudaGetSymbolAddress((void**)&xc,  g_xc);
    cudaGetSymbolAddress((void**)&dbc, g_dbc);
    cudaGetSymbolAddress((void**)&dt,  g_dt);
    cudaGetSymbolAddress((void**)&yg,  g_yg);
    cudaGetSymbolAddress((void**)&hs,  g_hs);

    dim3 thr(256);

    // 1. h = x @ W_enc^T + b_enc   (4096 x 1024 x 128)
    gemm_tn<1><<<dim3(DM/64, Mrows/64), thr>>>(x, OBS, W_enc, h, DM,
                                               Mrows, DM, OBS, b_enc);
    // 2. xz = h @ W_in^T           (4096 x 4096 x 1024)
    gemm_tn<0><<<dim3((2*DI)/64, Mrows/64), thr>>>(h, DM, W_in, xz, 2*DI,
                                                   Mrows, 2*DI, DM, nullptr);
    // 3. depthwise causal conv + bias + silu -> xc
    conv_silu_kernel<<<dim3(Ll, Bb), thr>>>(xz, conv_w, conv_b, xc);

    // 4. dbc = xc @ W_xproj^T      (4096 x 96 x 2048)
    gemm_tn<0><<<dim3(2, Mrows/64), thr>>>(xc, DI, W_xproj, dbc, 96,
                                           Mrows, 96, DI, nullptr);
    // 5. dt = softplus(dbc[:, :64] @ W_dtproj^T + dt_bias)  (4096 x 2048 x 64)
    gemm_tn<2><<<dim3(DI/64, Mrows/64), thr>>>(dbc, 96, W_dtproj, dt, DI,
                                               Mrows, DI, DTR, dt_bias);
    // 6. selective scan + skip + gate -> yg
    scan_kernel<<<Bb * 32, thr>>>(xc, dt, dbc, xz, A_log, D_skip, yg);

    // 7. hs = yg @ W_out^T         (4096 x 1024 x 2048)
    gemm_tn<0><<<dim3(DM/64, Mrows/64), thr>>>(yg, DI, W_out, hs, DM,
                                               Mrows, DM, DI, nullptr);
    // 8. recon = hs @ W_dec^T + b_dec -> out[0 : 4096*128]
    gemm_tn<1><<<dim3(OBS/64, Mrows/64), thr>>>(hs, DM, W_dec, out, OBS,
                                                Mrows, OBS, DM, b_dec);
    // 9. lat = hs @ W_lat^T + b_lat -> out[4096*128 : ]
    gemm_tn<1><<<dim3(1, Mrows/64), thr>>>(hs, DM, W_lat,
                                           out + (size_t)Mrows * OBS, LAT,
                                           Mrows, LAT, DM, b_lat);
    (void)in_sizes; (void)n_in; (void)out_size;
}

// round 4
// speedup vs baseline: 1.8215x; 1.8215x over previous
#include <cuda_runtime.h>
#include <cuda_bf16.h>
#include <math.h>
#include <stdint.h>

// Problem constants
#define Bb 4
#define Ll 1024
#define OBS 128
#define DM 1024
#define LAT 16
#define DS 16
#define DC 4
#define DI 2048          // 2*DM
#define DTR 64           // DM/16
#define Mrows 4096       // B*L

typedef __nv_bfloat16 bf16;

// ---------------- scratch (device globals; no allocation allowed) ----------
__device__ float g_xz [(size_t)Mrows * (2*DI)];    // 64 MB
__device__ float g_xc [(size_t)Mrows * DI];        // 32 MB
__device__ float g_dbc[(size_t)Mrows * 128];       // padded to 128 cols
__device__ float g_dt [(size_t)Mrows * DI];        // 32 MB
__device__ float g_hs [(size_t)Mrows * DM];        // 16 MB

__device__ bf16 g_xh  [(size_t)Mrows * OBS];
__device__ bf16 g_xl  [(size_t)Mrows * OBS];
__device__ bf16 g_weh [(size_t)DM * OBS];
__device__ bf16 g_wel [(size_t)DM * OBS];
__device__ bf16 g_hh  [(size_t)Mrows * DM];
__device__ bf16 g_hl  [(size_t)Mrows * DM];
__device__ bf16 g_winh[(size_t)(2*DI) * DM];
__device__ bf16 g_winl[(size_t)(2*DI) * DM];
__device__ bf16 g_xch [(size_t)Mrows * DI];
__device__ bf16 g_xcl [(size_t)Mrows * DI];
__device__ bf16 g_wxh [(size_t)128 * DI];          // W_xproj padded 96->128
__device__ bf16 g_wxl [(size_t)128 * DI];
__device__ bf16 g_dbch[(size_t)Mrows * 128];
__device__ bf16 g_dbcl[(size_t)Mrows * 128];
__device__ bf16 g_wdth[(size_t)DI * DTR];
__device__ bf16 g_wdtl[(size_t)DI * DTR];
__device__ bf16 g_ygh [(size_t)Mrows * DI];
__device__ bf16 g_ygl [(size_t)Mrows * DI];
__device__ bf16 g_wouth[(size_t)DM * DI];
__device__ bf16 g_woutl[(size_t)DM * DI];
__device__ bf16 g_hsh [(size_t)Mrows * DM];
__device__ bf16 g_hsl [(size_t)Mrows * DM];
__device__ bf16 g_wdech[(size_t)OBS * DM];
__device__ bf16 g_wdecl[(size_t)OBS * DM];

// ======================= low-level helpers =================================
__device__ __forceinline__ uint32_t smem_u32(const void* p) {
    uint32_t a;
    asm("{ .reg .u64 t; cvta.to.shared.u64 t, %1; cvt.u32.u64 %0, t; }"
        : "=r"(a) : "l"(p));
    return a;
}
#define CP_ASYNC16(dst, src) \
    asm volatile("cp.async.cg.shared.global [%0], [%1], 16;" :: "r"(dst), "l"(src) : "memory")
#define CP_COMMIT() asm volatile("cp.async.commit_group;" ::: "memory")

#define SWZ128(x) ((x) ^ (((x) >> 3) & 0x70))

__device__ __forceinline__ void ldsm4(uint32_t* r, uint32_t addr) {
    asm volatile("ldmatrix.sync.aligned.m8n8.x4.shared.b16 {%0,%1,%2,%3}, [%4];"
        : "=r"(r[0]), "=r"(r[1]), "=r"(r[2]), "=r"(r[3]) : "r"(addr));
}
__device__ __forceinline__ void ldsm2(uint32_t* r, uint32_t addr) {
    asm volatile("ldmatrix.sync.aligned.m8n8.x2.shared.b16 {%0,%1}, [%2];"
        : "=r"(r[0]), "=r"(r[1]) : "r"(addr));
}
__device__ __forceinline__ void mma16816(float* c, const uint32_t* a, const uint32_t* b) {
    asm volatile("mma.sync.aligned.m16n8k16.row.col.f32.bf16.bf16.f32 "
        "{%0,%1,%2,%3}, {%4,%5,%6,%7}, {%8,%9}, {%0,%1,%2,%3};"
        : "+f"(c[0]), "+f"(c[1]), "+f"(c[2]), "+f"(c[3])
        : "r"(a[0]), "r"(a[1]), "r"(a[2]), "r"(a[3]), "r"(b[0]), "r"(b[1]));
}
__device__ __forceinline__ void split1(float v, bf16& hi, bf16& lo) {
    hi = __float2bfloat16(v);
    lo = __float2bfloat16(v - __bfloat162float(hi));
}

// ============ split fp32 -> (bf16 hi, bf16 lo), contiguous ================
__global__ __launch_bounds__(256)
void split_kernel(const float* __restrict__ x,
                  bf16* __restrict__ xh, bf16* __restrict__ xl, int n)
{
    int i = blockIdx.x * 256 + threadIdx.x;
    if (i < n) { bf16 h, l; split1(x[i], h, l); xh[i] = h; xl[i] = l; }
}

// pad rows: src (srows x cols) -> dst (prows x cols), zero-filled tail rows
__global__ __launch_bounds__(256)
void split_pad_kernel(const float* __restrict__ x,
                      bf16* __restrict__ xh, bf16* __restrict__ xl,
                      int srows, int cols, int prows)
{
    int i = blockIdx.x * 256 + threadIdx.x;
    if (i < prows * cols) {
        int r = i / cols;
        float v = (r < srows) ? x[i] : 0.f;
        bf16 h, l; split1(v, h, l);
        xh[i] = h; xl[i] = l;
    }
}

// ======== split-bf16 mma.sync GEMM: C(M,N) = A(M,K) @ W(N,K)^T ============
// 3 accumulation passes: Ah*Bh + Ah*Bl + Al*Bh (fp32 accumulator).
// Tile 128x128x64; 256 threads = 8 warps (2 x 4); cp.async double buffer.
// EPI: 0 none, 1 +bias, 2 softplus(acc+bias)
// OUT: bit0 -> write f32 C; bit1 -> write (Ch, Cl) bf16 split
#define SM_STAGE 32768

template<int EPI, int OUT>
__global__ __launch_bounds__(256)
void gemm_mma(const bf16* __restrict__ Ah, const bf16* __restrict__ Al,
              const bf16* __restrict__ Bh, const bf16* __restrict__ Bl,
              float* __restrict__ C, bf16* __restrict__ Ch, bf16* __restrict__ Cl,
              int lda, int ldb, int K, int ldc,
              const float* __restrict__ bias)
{
    extern __shared__ char smem[];
    const uint32_t sb = smem_u32(smem);
    const int tid = threadIdx.x;
    const int wid = tid >> 5, lid = tid & 31;
    const int wm = (wid >> 2) * 64;   // warp m offset in tile
    const int wn = (wid & 3) * 32;    // warp n offset in tile
    const int bm = blockIdx.y * 128, bn = blockIdx.x * 128;

    const int KC = K >> 6;
    const int nch = 3 * KC;

    float acc[4][4][4];
#pragma unroll
    for (int mi = 0; mi < 4; mi++)
#pragma unroll
        for (int ni = 0; ni < 4; ni++)
#pragma unroll
            for (int r = 0; r < 4; r++) acc[mi][ni][r] = 0.f;

    const int cu = tid & 7;           // 16B unit within 128B row
    const int rb = tid >> 3;          // 0..31 base row

    auto load_chunk = [&](int idx, int s) {
        const int p = idx / KC, kc = idx - p * KC;
        const bf16* pA = (p == 2) ? Al : Ah;
        const bf16* pB = (p == 1) ? Bl : Bh;
        const size_t ka = (size_t)kc * 64 + cu * 8;
        const uint32_t ab = sb + s * SM_STAGE;
        const uint32_t bb = ab + 16384;
#pragma unroll
        for (int v = 0; v < 4; v++) {
            int r = rb + v * 32;
            uint32_t so = SWZ128((uint32_t)(r * 128 + cu * 16));
            CP_ASYNC16(ab + so, pA + (size_t)(bm + r) * lda + ka);
            CP_ASYNC16(bb + so, pB + (size_t)(bn + r) * ldb + ka);
        }
        CP_COMMIT();
    };

    load_chunk(0, 0);

    for (int i = 0; i < nch; i++) {
        if (i + 1 < nch) load_chunk(i + 1, (i + 1) & 1);
        if (i + 1 < nch) { asm volatile("cp.async.wait_group 1;" ::: "memory"); }
        else             { asm volatile("cp.async.wait_group 0;" ::: "memory"); }
        __syncthreads();

        const uint32_t ab = sb + (i & 1) * SM_STAGE;
        const uint32_t bb = ab + 16384;
#pragma unroll
        for (int ks = 0; ks < 4; ks++) {
            uint32_t af[4][4], bfr[4][2];
#pragma unroll
            for (int mi = 0; mi < 4; mi++) {
                int row = wm + mi * 16 + (lid & 15);
                int col = ks * 32 + ((lid >> 4) << 4);
                ldsm4(af[mi], ab + SWZ128((uint32_t)(row * 128 + col)));
            }
#pragma unroll
            for (int ni = 0; ni < 4; ni++) {
                int row = wn + ni * 8 + (lid & 7);
                int col = ks * 32 + (((lid >> 3) & 1) << 4);
                ldsm2(bfr[ni], bb + SWZ128((uint32_t)(row * 128 + col)));
            }
#pragma unroll
            for (int mi = 0; mi < 4; mi++)
#pragma unroll
                for (int ni = 0; ni < 4; ni++)
                    mma16816(acc[mi][ni], af[mi], bfr[ni]);
        }
        __syncthreads();
    }

    // ---------------- epilogue ----------------
    const int l4 = lid >> 2, l2 = (lid & 3) * 2;
#pragma unroll
    for (int mi = 0; mi < 4; mi++) {
#pragma unroll
        for (int half = 0; half < 2; half++) {
            int gr = bm + wm + mi * 16 + l4 + half * 8;
#pragma unroll
            for (int ni = 0; ni < 4; ni++) {
                int gc = bn + wn + ni * 8 + l2;
                float v0 = acc[mi][ni][half * 2 + 0];
                float v1 = acc[mi][ni][half * 2 + 1];
                if (EPI >= 1) { v0 += bias[gc]; v1 += bias[gc + 1]; }
                if (EPI == 2) {
                    v0 = fmaxf(v0, 0.f) + log1pf(__expf(-fabsf(v0)));
                    v1 = fmaxf(v1, 0.f) + log1pf(__expf(-fabsf(v1)));
                }
                size_t off = (size_t)gr * ldc + gc;
                if (OUT & 1) {
                    float2 f2; f2.x = v0; f2.y = v1;
                    *(float2*)(C + off) = f2;
                }
                if (OUT & 2) {
                    bf16 h0, l0, h1, l1;
                    split1(v0, h0, l0); split1(v1, h1, l1);
                    __nv_bfloat162 hh2; hh2.x = h0; hh2.y = h1;
                    __nv_bfloat162 ll2; ll2.x = l0; ll2.y = l1;
                    *(__nv_bfloat162*)(Ch + off) = hh2;
                    *(__nv_bfloat162*)(Cl + off) = ll2;
                }
            }
        }
    }
}

// ---------------- small fp32 GEMM (kept for lat, N=16) ---------------------
template<int EPI>
__global__ __launch_bounds__(256)
void gemm_tn(const float* __restrict__ A, int lda,
             const float* __restrict__ W,
             float* __restrict__ C, int ldc,
             int M, int N, int K,
             const float* __restrict__ bias)
{
    const int BM = 64, BN = 64, BK = 16;
    __shared__ float As[BK][BM + 4];
    __shared__ float Ws[BK][BN + 4];

    const int bm = blockIdx.y * BM;
    const int bn = blockIdx.x * BN;
    const int tid = threadIdx.x;
    const int tm = tid >> 4;
    const int tn = tid & 15;

    float acc[4][4];
#pragma unroll
    for (int i = 0; i < 4; i++)
#pragma unroll
        for (int j = 0; j < 4; j++) acc[i][j] = 0.f;

    for (int k0 = 0; k0 < K; k0 += BK) {
#pragma unroll
        for (int i = 0; i < 4; i++) {
            int e = tid + i * 256;
            int r = e >> 4, c = e & 15;
            int gm = bm + r;
            float v = 0.f;
            if (gm < M) v = A[(size_t)gm * lda + (k0 + c)];
            As[c][r] = v;
        }
#pragma unroll
        for (int i = 0; i < 4; i++) {
            int e = tid + i * 256;
            int r = e >> 4, c = e & 15;
            int gn = bn + r;
            float v = 0.f;
            if (gn < N) v = W[(size_t)gn * K + (k0 + c)];
            Ws[c][r] = v;
        }
        __syncthreads();

#pragma unroll
        for (int kk = 0; kk < BK; kk++) {
            float ra[4], rbv[4];
#pragma unroll
            for (int i = 0; i < 4; i++) ra[i] = As[kk][tm * 4 + i];
#pragma unroll
            for (int j = 0; j < 4; j++) rbv[j] = Ws[kk][tn * 4 + j];
#pragma unroll
            for (int i = 0; i < 4; i++)
#pragma unroll
                for (int j = 0; j < 4; j++)
                    acc[i][j] = fmaf(ra[i], rbv[j], acc[i][j]);
        }
        __syncthreads();
    }

#pragma unroll
    for (int i = 0; i < 4; i++) {
        int gm = bm + tm * 4 + i;
        if (gm >= M) continue;
#pragma unroll
        for (int j = 0; j < 4; j++) {
            int gn = bn + tn * 4 + j;
            if (gn >= N) continue;
            float v = acc[i][j];
            if (EPI >= 1) v += bias[gn];
            C[(size_t)gm * ldc + gn] = v;
        }
    }
}

// ---------- depthwise causal conv + bias + silu; emits f32 + bf16 split ----
__global__ __launch_bounds__(256)
void conv_silu_kernel(const float* __restrict__ xz,
                      const float* __restrict__ conv_w,
                      const float* __restrict__ conv_b,
                      float* __restrict__ xc,
                      bf16* __restrict__ xch, bf16* __restrict__ xcl)
{
    int t = blockIdx.x;
    int b = blockIdx.y;
    size_t outbase = ((size_t)b * Ll + t) * DI;
    for (int d = threadIdx.x; d < DI; d += 256) {
        float acc = conv_b[d];
        const float* w = conv_w + d * DC;
#pragma unroll
        for (int j = 0; j < DC; j++) {
            int tt = t - (DC - 1) + j;
            if (tt >= 0)
                acc = fmaf(w[j], xz[((size_t)b * Ll + tt) * (2 * DI) + d], acc);
        }
        float s = acc / (1.f + __expf(-acc));
        xc[outbase + d] = s;
        bf16 h, l; split1(s, h, l);
        xch[outbase + d] = h;
        xcl[outbase + d] = l;
    }
}

// ---------------- selective scan; emits gated output as bf16 split ---------
#define TCH 128
__global__ __launch_bounds__(256)
void scan_kernel(const float* __restrict__ xc,
                 const float* __restrict__ dtb,
                 const float* __restrict__ dbc,   // ldc = 128 (padded)
                 const float* __restrict__ xz,
                 const float* __restrict__ A_log,
                 const float* __restrict__ D_skip,
                 bf16* __restrict__ ygh, bf16* __restrict__ ygl)
{
    const int b    = blockIdx.x >> 5;
    const int dblk = blockIdx.x & 31;
    const int tid  = threadIdx.x;
    const int q    = tid & 3;
    const int dl   = tid >> 2;
    const int d    = dblk * 64 + dl;

    float Areg[4], s[4];
#pragma unroll
    for (int j = 0; j < 4; j++) {
        Areg[j] = -__expf(A_log[(size_t)d * DS + q * 4 + j]);
        s[j] = 0.f;
    }
    const float Dv = D_skip[d];

    __shared__ float BC[TCH][32];

    for (int t0 = 0; t0 < Ll; t0 += TCH) {
        __syncthreads();
        for (int e = tid; e < TCH * 32; e += 256) {
            int tt = e >> 5, c = e & 31;
            BC[tt][c] = dbc[((size_t)b * Ll + t0 + tt) * 128 + DTR + c];
        }
        __syncthreads();

        for (int ti = 0; ti < TCH; ti++) {
            size_t row = (size_t)b * Ll + t0 + ti;
            float u   = xc [row * DI + d];
            float dtv = dtb[row * DI + d];
            float du  = dtv * u;
            float y = 0.f;
#pragma unroll
            for (int j = 0; j < 4; j++) {
                float e = __expf(dtv * Areg[j]);
                s[j] = fmaf(s[j], e, du * BC[ti][q * 4 + j]);
                y = fmaf(s[j], BC[ti][16 + q * 4 + j], y);
            }
            y += __shfl_xor_sync(0xffffffffu, y, 1);
            y += __shfl_xor_sync(0xffffffffu, y, 2);
            if (q == 0) {
                float z = xz[row * (2 * DI) + DI + d];
                float g = z / (1.f + __expf(-z));
                float val = (y + u * Dv) * g;
                bf16 h, l; split1(val, h, l);
                ygh[row * DI + d] = h;
                ygl[row * DI + d] = l;
            }
        }
    }
}

// ---------------- launch ---------------------------------------------------
extern "C" void kernel_launch(void* const* d_in, const int* in_sizes, int n_in,
                              void* d_out, int out_size)
{
    const float* x        = (const float*)d_in[0];
    const float* W_enc    = (const float*)d_in[1];
    const float* b_enc    = (const float*)d_in[2];
    const float* W_in     = (const float*)d_in[3];
    const float* conv_w   = (const float*)d_in[4];
    const float* conv_b   = (const float*)d_in[5];
    const float* W_xproj  = (const float*)d_in[6];
    const float* W_dtproj = (const float*)d_in[7];
    const float* dt_bias  = (const float*)d_in[8];
    const float* A_log    = (const float*)d_in[9];
    const float* D_skip   = (const float*)d_in[10];
    const float* W_out    = (const float*)d_in[11];
    const float* W_dec    = (const float*)d_in[12];
    const float* b_dec    = (const float*)d_in[13];
    const float* W_lat    = (const float*)d_in[14];
    const float* b_lat    = (const float*)d_in[15];
    float* out = (float*)d_out;

    float *xz, *xc, *dbc, *dt, *hs;
    cudaGetSymbolAddress((void**)&xz,  g_xz);
    cudaGetSymbolAddress((void**)&xc,  g_xc);
    cudaGetSymbolAddress((void**)&dbc, g_dbc);
    cudaGetSymbolAddress((void**)&dt,  g_dt);
    cudaGetSymbolAddress((void**)&hs,  g_hs);

    bf16 *xh,*xl,*weh,*wel,*hh,*hl,*winh,*winl,*xch,*xcl,*wxh,*wxl;
    bf16 *dbch,*dbcl,*wdth,*wdtl,*ygh,*ygl,*wouth,*woutl,*hsh,*hsl,*wdech,*wdecl;
    cudaGetSymbolAddress((void**)&xh,   g_xh);   cudaGetSymbolAddress((void**)&xl,   g_xl);
    cudaGetSymbolAddress((void**)&weh,  g_weh);  cudaGetSymbolAddress((void**)&wel,  g_wel);
    cudaGetSymbolAddress((void**)&hh,   g_hh);   cudaGetSymbolAddress((void**)&hl,   g_hl);
    cudaGetSymbolAddress((void**)&winh, g_winh); cudaGetSymbolAddress((void**)&winl, g_winl);
    cudaGetSymbolAddress((void**)&xch,  g_xch);  cudaGetSymbolAddress((void**)&xcl,  g_xcl);
    cudaGetSymbolAddress((void**)&wxh,  g_wxh);  cudaGetSymbolAddress((void**)&wxl,  g_wxl);
    cudaGetSymbolAddress((void**)&dbch, g_dbch); cudaGetSymbolAddress((void**)&dbcl, g_dbcl);
    cudaGetSymbolAddress((void**)&wdth, g_wdth); cudaGetSymbolAddress((void**)&wdtl, g_wdtl);
    cudaGetSymbolAddress((void**)&ygh,  g_ygh);  cudaGetSymbolAddress((void**)&ygl,  g_ygl);
    cudaGetSymbolAddress((void**)&wouth,g_wouth);cudaGetSymbolAddress((void**)&woutl,g_woutl);
    cudaGetSymbolAddress((void**)&hsh,  g_hsh);  cudaGetSymbolAddress((void**)&hsl,  g_hsl);
    cudaGetSymbolAddress((void**)&wdech,g_wdech);cudaGetSymbolAddress((void**)&wdecl,g_wdecl);

    const int GSM = 2 * SM_STAGE;   // 64 KB dynamic smem
    static int smem_set = 0;
    if (!smem_set) {
        cudaFuncSetAttribute(gemm_mma<1,2>, cudaFuncAttributeMaxDynamicSharedMemorySize, GSM);
        cudaFuncSetAttribute(gemm_mma<0,1>, cudaFuncAttributeMaxDynamicSharedMemorySize, GSM);
        cudaFuncSetAttribute(gemm_mma<0,3>, cudaFuncAttributeMaxDynamicSharedMemorySize, GSM);
        cudaFuncSetAttribute(gemm_mma<2,1>, cudaFuncAttributeMaxDynamicSharedMemorySize, GSM);
        cudaFuncSetAttribute(gemm_mma<1,1>, cudaFuncAttributeMaxDynamicSharedMemorySize, GSM);
        smem_set = 1;
    }

    dim3 thr(256);

    // ---- weight / input splits -------------------------------------------
    split_kernel<<<(Mrows*OBS + 255)/256, thr>>>(x, xh, xl, Mrows*OBS);
    split_kernel<<<(DM*OBS + 255)/256, thr>>>(W_enc, weh, wel, DM*OBS);
    split_kernel<<<((2*DI)*DM + 255)/256, thr>>>(W_in, winh, winl, (2*DI)*DM);
    split_pad_kernel<<<(128*DI + 255)/256, thr>>>(W_xproj, wxh, wxl, 96, DI, 128);
    split_kernel<<<(DI*DTR + 255)/256, thr>>>(W_dtproj, wdth, wdtl, DI*DTR);
    split_kernel<<<(DM*DI + 255)/256, thr>>>(W_out, wouth, woutl, DM*DI);
    split_kernel<<<(OBS*DM + 255)/256, thr>>>(W_dec, wdech, wdecl, OBS*DM);

    // 1. h = x @ W_enc^T + b_enc  (4096x1024x128) -> bf16 split only
    gemm_mma<1,2><<<dim3(DM/128, Mrows/128), thr, GSM>>>(
        xh, xl, weh, wel, nullptr, hh, hl, OBS, OBS, OBS, DM, b_enc);

    // 2. xz = h @ W_in^T  (4096x4096x1024) -> f32
    gemm_mma<0,1><<<dim3((2*DI)/128, Mrows/128), thr, GSM>>>(
        hh, hl, winh, winl, xz, nullptr, nullptr, DM, DM, DM, 2*DI, nullptr);

    // 3. conv + bias + silu -> xc (f32 + bf16 split)
    conv_silu_kernel<<<dim3(Ll, Bb), thr>>>(xz, conv_w, conv_b, xc, xch, xcl);

    // 4. dbc = xc @ W_xproj^T (N padded to 128) -> f32 + bf16 split
    gemm_mma<0,3><<<dim3(1, Mrows/128), thr, GSM>>>(
        xch, xcl, wxh, wxl, dbc, dbch, dbcl, DI, DI, DI, 128, nullptr);

    // 5. dt = softplus(dbc[:, :64] @ W_dtproj^T + dt_bias)  (4096x2048x64)
    gemm_mma<2,1><<<dim3(DI/128, Mrows/128), thr, GSM>>>(
        dbch, dbcl, wdth, wdtl, dt, nullptr, nullptr, 128, DTR, DTR, DI, dt_bias);

    // 6. selective scan + skip + gate -> yg (bf16 split)
    scan_kernel<<<Bb * 32, thr>>>(xc, dt, dbc, xz, A_log, D_skip, ygh, ygl);

    // 7. hs = yg @ W_out^T  (4096x1024x2048) -> f32 + bf16 split
    gemm_mma<0,3><<<dim3(DM/128, Mrows/128), thr, GSM>>>(
        ygh, ygl, wouth, woutl, hs, hsh, hsl, DI, DI, DI, DM, nullptr);

    // 8. recon = hs @ W_dec^T + b_dec  (4096x128x1024) -> out
    gemm_mma<1,1><<<dim3(OBS/128, Mrows/128), thr, GSM>>>(
        hsh, hsl, wdech, wdecl, out, nullptr, nullptr, DM, DM, DM, OBS, b_dec);

    // 9. lat = hs @ W_lat^T + b_lat  (4096x16x1024)  fp32
    gemm_tn<1><<<dim3(1, Mrows/64), thr>>>(hs, DM, W_lat,
                                           out + (size_t)Mrows * OBS, LAT,
                                           Mrows, LAT, DM, b_lat);
    (void)in_sizes; (void)n_in; (void)out_size;
}